// round 4
// baseline (speedup 1.0000x reference)
#include <cuda_runtime.h>
#include <cstdint>
#include <cstddef>

#define D 768
#define N_LAYERS 4
#define MAXN 50000
#define MAXE 100000

// ---------------- static scratch (allocation-free rule) ----------------
__device__ float g_e  [(size_t)MAXE * D];   // bond/edge features e  [E,768]
__device__ float g_tmp[(size_t)MAXE * D];   // GEMM hidden buffer   [E,768]
__device__ float g_hA [(size_t)MAXN * D];
__device__ float g_hB [(size_t)MAXN * D];
__device__ float g_agg[(size_t)MAXN * D];

// ---------------- helpers ----------------
__device__ __forceinline__ float gelu_f(float x) {
    const float k0 = 0.7978845608028654f;   // sqrt(2/pi)
    const float k1 = 0.044715f;
    return 0.5f * x * (1.0f + tanhf(k0 * (x + k1 * x * x * x)));
}

template <int ACT>
__device__ __forceinline__ float actf(float x) {
    if (ACT == 1) return fmaxf(x, 0.0f);
    if (ACT == 2) return gelu_f(x);
    return x;
}

// 256-thread block reduction of (sum, sumsq). shm must hold 16 floats.
__device__ __forceinline__ void block_reduce2(float& s1, float& s2, float* shm) {
    #pragma unroll
    for (int o = 16; o > 0; o >>= 1) {
        s1 += __shfl_xor_sync(0xffffffffu, s1, o);
        s2 += __shfl_xor_sync(0xffffffffu, s2, o);
    }
    int wid = threadIdx.x >> 5, lane = threadIdx.x & 31;
    if (lane == 0) { shm[wid] = s1; shm[8 + wid] = s2; }
    __syncthreads();
    float a = 0.f, b = 0.f;
    #pragma unroll
    for (int i = 0; i < 8; i++) { a += shm[i]; b += shm[8 + i]; }
    s1 = a; s2 = b;
}

// ---------------- embedding sum + LayerNorm ----------------
// one block (256 threads) per row; each thread owns 3 of 768 features
__global__ void embed_ln_kernel(const int* __restrict__ ids,
                                const float* __restrict__ emb,
                                const float* __restrict__ g,
                                const float* __restrict__ bta,
                                float* __restrict__ out,
                                int F, int V) {
    int n = blockIdx.x;
    int t = threadIdx.x;
    __shared__ int   sid[16];
    __shared__ float shm[16];
    if (t < F) sid[t] = ids[(size_t)n * F + t];
    __syncthreads();

    float x[3];
    #pragma unroll
    for (int j = 0; j < 3; j++) {
        int d = t + j * 256;
        float s = 0.f;
        for (int f = 0; f < F; f++)
            s += emb[((size_t)(f * V + sid[f])) * D + d];
        x[j] = s;
    }
    float s1 = x[0] + x[1] + x[2];
    float s2 = x[0]*x[0] + x[1]*x[1] + x[2]*x[2];
    block_reduce2(s1, s2, shm);
    float mean = s1 * (1.0f / D);
    float var  = s2 * (1.0f / D) - mean * mean;
    float inv  = rsqrtf(var + 1e-5f);
    float* o = out + (size_t)n * D;
    #pragma unroll
    for (int j = 0; j < 3; j++) {
        int d = t + j * 256;
        o[d] = (x[j] - mean) * inv * g[d] + bta[d];
    }
}

// ---------------- edge message: agg[dst] += relu(h[src] + e) ----------------
__global__ void edge_msg_kernel(const int* __restrict__ ei,
                                const float* __restrict__ h,
                                const float* __restrict__ e,
                                float* __restrict__ agg, int E) {
    int eid = blockIdx.x;
    int src = __ldg(ei + eid);
    int dst = __ldg(ei + E + eid);
    int t = threadIdx.x;  // 192 threads * float4 = 768
    float4 hv = *((const float4*)(h + (size_t)src * D) + t);
    float4 ev = *((const float4*)(e + (size_t)eid * D) + t);
    float4 m;
    m.x = fmaxf(hv.x + ev.x, 0.f);
    m.y = fmaxf(hv.y + ev.y, 0.f);
    m.z = fmaxf(hv.z + ev.z, 0.f);
    m.w = fmaxf(hv.w + ev.w, 0.f);
    float* a = agg + (size_t)dst * D + t * 4;
    atomicAdd(a + 0, m.x);
    atomicAdd(a + 1, m.y);
    atomicAdd(a + 2, m.z);
    atomicAdd(a + 3, m.w);
}

// ---------------- fused gelu + residual + LayerNorm (+ agg init for next layer) ----------------
__global__ void ln_res_kernel(const float* __restrict__ z,
                              const float* __restrict__ hin,
                              const float* __restrict__ g,
                              const float* __restrict__ bta,
                              float* __restrict__ out,
                              float* __restrict__ aggc) {
    int n = blockIdx.x;
    int t = threadIdx.x;
    __shared__ float shm[16];
    float x[3];
    #pragma unroll
    for (int j = 0; j < 3; j++) {
        int d = t + j * 256;
        x[j] = gelu_f(z[(size_t)n * D + d]) + hin[(size_t)n * D + d];
    }
    float s1 = x[0] + x[1] + x[2];
    float s2 = x[0]*x[0] + x[1]*x[1] + x[2]*x[2];
    block_reduce2(s1, s2, shm);
    float mean = s1 * (1.0f / D);
    float var  = s2 * (1.0f / D) - mean * mean;
    float inv  = rsqrtf(var + 1e-5f);
    #pragma unroll
    for (int j = 0; j < 3; j++) {
        int d = t + j * 256;
        float r = (x[j] - mean) * inv * g[d] + bta[d];
        out[(size_t)n * D + d] = r;
        if (aggc) aggc[(size_t)n * D + d] = r;
    }
}

__global__ void copy_kernel(const float4* __restrict__ src, float4* __restrict__ dst, int n4) {
    int i = blockIdx.x * blockDim.x + threadIdx.x;
    if (i < n4) dst[i] = src[i];
}

// ---------------- tf32 tensor-core GEMM ----------------
// C[M,768] = act(A[M,768] @ W[768,768] + bias), W row-major [K,N]
#define BM 128
#define BN 128
#define BK 32
#define SA_S 36    // A smem stride (floats): (lane/4)*36 + lane%4 -> banks 4*(lane/4)+lane%4, conflict-free
#define SB_S 136   // B smem stride: 136 mod 32 = 8 -> 8*(lane%4)+lane/4, conflict-free
#define NSTAGE 3
#define GEMM_THREADS 256
#define GEMM_SMEM (NSTAGE * (BM * SA_S + BK * SB_S) * 4)   // 107520 bytes

__device__ __forceinline__ void cp_async16(float* s, const float* gm) {
    uint32_t sa = (uint32_t)__cvta_generic_to_shared(s);
    asm volatile("cp.async.cg.shared.global [%0], [%1], 16;\n" :: "r"(sa), "l"(gm));
}
__device__ __forceinline__ uint32_t f2tf(float x) {
    uint32_t r;
    asm("cvt.rna.tf32.f32 %0, %1;" : "=r"(r) : "f"(x));
    return r;
}
__device__ __forceinline__ void mma_tf32(float* c, const uint32_t* a, uint32_t b0, uint32_t b1) {
    asm volatile(
        "mma.sync.aligned.m16n8k8.row.col.f32.tf32.tf32.f32 "
        "{%0,%1,%2,%3},{%4,%5,%6,%7},{%8,%9},{%0,%1,%2,%3};"
        : "+f"(c[0]), "+f"(c[1]), "+f"(c[2]), "+f"(c[3])
        : "r"(a[0]), "r"(a[1]), "r"(a[2]), "r"(a[3]), "r"(b0), "r"(b1));
}

template <int ACT>
__global__ void __launch_bounds__(GEMM_THREADS, 2)
gemm_kernel(const float* __restrict__ A, const float* __restrict__ W,
            const float* __restrict__ bias, float* __restrict__ C, int M) {
    extern __shared__ float smem[];
    const int t  = threadIdx.x;
    const int m0 = blockIdx.y * BM;
    const int n0 = blockIdx.x * BN;
    float* sA = smem;
    float* sB = smem + NSTAGE * BM * SA_S;

    const int NT = D / BK;  // 24

    auto load_stage = [&](int st, int kt) {
        float* a = sA + st * BM * SA_S;
        float* b = sB + st * BK * SB_S;
        #pragma unroll
        for (int i = 0; i < 4; i++) {
            int q = t + i * GEMM_THREADS;
            int row = q >> 3, c4 = (q & 7) << 2;
            int m = m0 + row;
            m = (m < M) ? m : (M - 1);   // clamp: garbage rows never stored
            cp_async16(a + row * SA_S + c4, A + (size_t)m * D + kt * BK + c4);
        }
        #pragma unroll
        for (int i = 0; i < 4; i++) {
            int q = t + i * GEMM_THREADS;
            int row = q >> 5, c4 = (q & 31) << 2;
            cp_async16(b + row * SB_S + c4, W + (size_t)(kt * BK + row) * D + n0 + c4);
        }
    };

    float acc[2][8][4];
    #pragma unroll
    for (int i = 0; i < 2; i++)
        #pragma unroll
        for (int j = 0; j < 8; j++)
            #pragma unroll
            for (int k = 0; k < 4; k++) acc[i][j][k] = 0.f;

    load_stage(0, 0); asm volatile("cp.async.commit_group;\n" ::: "memory");
    load_stage(1, 1); asm volatile("cp.async.commit_group;\n" ::: "memory");

    const int lane = t & 31, wid = t >> 5;
    const int wm = (wid & 3) * 32;     // 4 warps along M
    const int wn = (wid >> 2) * 64;    // 2 warps along N
    const int gr = lane >> 2, tig = lane & 3;

    for (int kt = 0; kt < NT; ++kt) {
        asm volatile("cp.async.wait_group 1;\n" ::: "memory");
        __syncthreads();
        int st = kt % NSTAGE;
        const float* a = sA + st * BM * SA_S;
        const float* b = sB + st * BK * SB_S;
        #pragma unroll
        for (int kk = 0; kk < BK; kk += 8) {
            uint32_t af[2][4];
            #pragma unroll
            for (int mi = 0; mi < 2; mi++) {
                int r = wm + mi * 16 + gr;
                af[mi][0] = f2tf(a[r * SA_S + kk + tig]);
                af[mi][1] = f2tf(a[(r + 8) * SA_S + kk + tig]);
                af[mi][2] = f2tf(a[r * SA_S + kk + tig + 4]);
                af[mi][3] = f2tf(a[(r + 8) * SA_S + kk + tig + 4]);
            }
            #pragma unroll
            for (int ni = 0; ni < 8; ni++) {
                int c = wn + ni * 8 + gr;
                uint32_t b0 = f2tf(b[(kk + tig) * SB_S + c]);
                uint32_t b1 = f2tf(b[(kk + tig + 4) * SB_S + c]);
                mma_tf32(acc[0][ni], af[0], b0, b1);
                mma_tf32(acc[1][ni], af[1], b0, b1);
            }
        }
        int ktn = kt + 2;
        if (ktn < NT) load_stage(ktn % NSTAGE, ktn);
        asm volatile("cp.async.commit_group;\n" ::: "memory");
    }

    // epilogue: bias + activation + store
    #pragma unroll
    for (int mi = 0; mi < 2; mi++) {
        int row0 = m0 + wm + mi * 16 + gr;
        #pragma unroll
        for (int ni = 0; ni < 8; ni++) {
            int col = n0 + wn + ni * 8 + tig * 2;
            float bv0 = bias[col], bv1 = bias[col + 1];
            float v0 = actf<ACT>(acc[mi][ni][0] + bv0);
            float v1 = actf<ACT>(acc[mi][ni][1] + bv1);
            float v2 = actf<ACT>(acc[mi][ni][2] + bv0);
            float v3 = actf<ACT>(acc[mi][ni][3] + bv1);
            if (row0 < M)
                *(float2*)(C + (size_t)row0 * D + col) = make_float2(v0, v1);
            if (row0 + 8 < M)
                *(float2*)(C + (size_t)(row0 + 8) * D + col) = make_float2(v2, v3);
        }
    }
}

// ---------------- host orchestration ----------------
extern "C" void kernel_launch(void* const* d_in, const int* in_sizes, int n_in,
                              void* d_out, int out_size) {
    const int*   x          = (const int*)d_in[0];
    const int*   edge_attr  = (const int*)d_in[1];
    const int*   edge_index = (const int*)d_in[2];
    const float* atom_emb   = (const float*)d_in[3];
    const float* atom_ln_g  = (const float*)d_in[4];
    const float* atom_ln_b  = (const float*)d_in[5];
    const float* atom_w1    = (const float*)d_in[6];
    const float* atom_b1    = (const float*)d_in[7];
    const float* atom_w2    = (const float*)d_in[8];
    const float* atom_b2    = (const float*)d_in[9];
    const float* bond_emb   = (const float*)d_in[10];
    const float* bond_ln_g  = (const float*)d_in[11];
    const float* bond_ln_b  = (const float*)d_in[12];
    const float* bond_w1    = (const float*)d_in[13];
    const float* bond_b1    = (const float*)d_in[14];
    const float* bond_w2    = (const float*)d_in[15];
    const float* bond_b2    = (const float*)d_in[16];
    const float* conv_w1    = (const float*)d_in[17];
    const float* conv_b1    = (const float*)d_in[18];
    const float* conv_w2    = (const float*)d_in[19];
    const float* conv_b2    = (const float*)d_in[20];
    const float* ln_g       = (const float*)d_in[21];
    const float* ln_b       = (const float*)d_in[22];
    float* out = (float*)d_out;

    int N = in_sizes[0] / 9;
    int E = in_sizes[1] / 3;
    if (N > MAXN) N = MAXN;
    if (E > MAXE) E = MAXE;

    float *pe, *ptmp, *phA, *phB, *pagg;
    cudaGetSymbolAddress((void**)&pe,   g_e);
    cudaGetSymbolAddress((void**)&ptmp, g_tmp);
    cudaGetSymbolAddress((void**)&phA,  g_hA);
    cudaGetSymbolAddress((void**)&phB,  g_hB);
    cudaGetSymbolAddress((void**)&pagg, g_agg);

    cudaFuncSetAttribute(gemm_kernel<0>, cudaFuncAttributeMaxDynamicSharedMemorySize, GEMM_SMEM);
    cudaFuncSetAttribute(gemm_kernel<1>, cudaFuncAttributeMaxDynamicSharedMemorySize, GEMM_SMEM);
    cudaFuncSetAttribute(gemm_kernel<2>, cudaFuncAttributeMaxDynamicSharedMemorySize, GEMM_SMEM);

    dim3 gridN(D / BN, (N + BM - 1) / BM);
    dim3 gridE(D / BN, (E + BM - 1) / BM);

    // ---- atom encode: h = enc(x) ----
    embed_ln_kernel<<<N, 256>>>(x, atom_emb, atom_ln_g, atom_ln_b, pagg, 9, 128);
    gemm_kernel<2><<<gridN, GEMM_THREADS, GEMM_SMEM>>>(pagg, atom_w1, atom_b1, ptmp, N);
    gemm_kernel<0><<<gridN, GEMM_THREADS, GEMM_SMEM>>>(ptmp, atom_w2, atom_b2, phA, N);

    // ---- bond encode: e = enc(edge_attr) ----
    embed_ln_kernel<<<E, 256>>>(edge_attr, bond_emb, bond_ln_g, bond_ln_b, pe, 3, 8);
    gemm_kernel<2><<<gridE, GEMM_THREADS, GEMM_SMEM>>>(pe, bond_w1, bond_b1, ptmp, E);
    gemm_kernel<0><<<gridE, GEMM_THREADS, GEMM_SMEM>>>(ptmp, bond_w2, bond_b2, pe, E);

    // ---- init agg = h for layer 0 ----
    int n4 = N * D / 4;
    copy_kernel<<<(n4 + 255) / 256, 256>>>((const float4*)phA, (float4*)pagg, n4);

    const float* hcur = phA;
    float* hnext = phB;
    for (int l = 0; l < N_LAYERS; l++) {
        // agg += relu(h[src] + e)   (agg pre-initialized to h -> z = h + sum msg)
        edge_msg_kernel<<<E, 192>>>(edge_index, hcur, pe, pagg, E);
        // conv MLP
        gemm_kernel<1><<<gridN, GEMM_THREADS, GEMM_SMEM>>>(pagg, conv_w1 + (size_t)l * D * D,
                                                           conv_b1 + l * D, ptmp, N);
        gemm_kernel<0><<<gridN, GEMM_THREADS, GEMM_SMEM>>>(ptmp, conv_w2 + (size_t)l * D * D,
                                                           conv_b2 + l * D, pagg, N);
        // h = LN(gelu(z) + h_in); also seed next layer's agg
        float* dst  = (l == N_LAYERS - 1) ? out : hnext;
        float* aggc = (l == N_LAYERS - 1) ? nullptr : pagg;
        ln_res_kernel<<<N, 256>>>(pagg, hcur, ln_g + l * D, ln_b + l * D, dst, aggc);

        float* old = (float*)hcur;
        hcur = dst;
        hnext = old;
    }
}